// round 7
// baseline (speedup 1.0000x reference)
#include <cuda_runtime.h>

// CovarianceLayer: x [64, 4, 8192, 16] fp32 -> cov [64, 4, 16, 16] fp32
// One CTA per (b,c), 256 threads, 2 CTAs/SM. NO smem / NO barriers in main loop:
// lanes 2r and 2r+1 of each warp both load row r's full 64B directly (duplicate
// addresses merge in the L1 coalescer -> 1x DRAM traffic); even lanes accumulate
// the even-m half of the 16x16 triangle, odd lanes the odd-m half, as packed
// f32x2 accumulators (40 ull = 80 regs). Depth-2 register prefetch hides LDG.

#define T_DIM    8192
#define M_DIM    16
#define NTHREADS 256
#define NU       40   // f32x2 units per parity half: 36 triangle + 4 column-sum

typedef unsigned long long ull;

__device__ __forceinline__ void fma2(ull& d, ull a, ull b) {
    asm("fma.rn.f32x2 %0, %1, %2, %0;" : "+l"(d) : "l"(a), "l"(b));
}
__device__ __forceinline__ void add2(ull& d, ull a) {
    asm("add.rn.f32x2 %0, %1, %0;" : "+l"(d) : "l"(a));
}
__device__ __forceinline__ float2 u2f(ull u) {
    float2 f; asm("mov.b64 {%0,%1}, %2;" : "=f"(f.x), "=f"(f.y) : "l"(u)); return f;
}
__device__ __forceinline__ ull f2u(float lo, float hi) {
    ull u; asm("mov.b64 %0, {%1,%2};" : "=l"(u) : "f"(lo), "f"(hi)); return u;
}

__host__ __device__ __forceinline__ int unit_base(int a) { return 8 * a - a * (a - 1) / 2; }

__device__ __forceinline__ void loadrow(ull v[8], const ulonglong2* __restrict__ p) {
    ulonglong2 q0 = p[0], q1 = p[1], q2 = p[2], q3 = p[3];   // 4x LDG.128
    v[0] = q0.x; v[1] = q0.y; v[2] = q1.x; v[3] = q1.y;
    v[4] = q2.x; v[5] = q2.y; v[6] = q3.x; v[7] = q3.y;
}

template <int E>   // E = lane parity: which element of pair a supplies vm
__device__ __forceinline__ void accum_row(ull acc[NU], const ull v[8]) {
    #pragma unroll
    for (int a = 0; a < 8; a++) {            // m = 2a + E
        float2 c = u2f(v[a]);
        const float vm = E ? c.y : c.x;
        const ull bm = f2u(vm, vm);
        #pragma unroll
        for (int j = a; j < 8; j++)
            fma2(acc[unit_base(a) + j - a], bm, v[j]);   // (vm*v[2j], vm*v[2j+1])
    }
    #pragma unroll
    for (int j = 0; j < 4; j++)              // column sums: parity owns 4 pairs
        add2(acc[36 + j], v[E * 4 + j]);
}

template <int E>
__device__ __forceinline__ void main_loop(ull acc[NU], const ulonglong2* __restrict__ rp) {
    ull A[8], B[8];
    loadrow(A, rp);                          // row s=0
    loadrow(B, rp + 512);                    // row s=1 (512 ulonglong2 = 128 rows)
    #pragma unroll 1
    for (int s = 0; s < 64; s += 2) {
        accum_row<E>(acc, A);
        if (s + 2 < 64) loadrow(A, rp + (size_t)(s + 2) * 512);
        accum_row<E>(acc, B);
        if (s + 3 < 64) loadrow(B, rp + (size_t)(s + 3) * 512);
    }
}

__global__ void __launch_bounds__(NTHREADS, 2)
cov_kernel(const float* __restrict__ x, float* __restrict__ out)
{
    __shared__ float red[8][4 * NU];   // per-warp: [0..79]=parity0, [80..159]=parity1
    __shared__ float tot[4 * NU];      // 160 combined sums

    const int bc  = blockIdx.x;
    const int tid = threadIdx.x;
    const int wid = tid >> 5;
    const int lid = tid & 31;
    const int e   = lid & 1;           // parity
    const int lr  = lid >> 1;          // local row 0..15

    // rows handled: s*128 + wid*16 + lr, s = 0..63
    const ulonglong2* __restrict__ rp =
        reinterpret_cast<const ulonglong2*>(x + (size_t)bc * T_DIM * M_DIM)
        + (size_t)(wid * 16 + lr) * 4;

    ull acc[NU];
    #pragma unroll
    for (int i = 0; i < NU; i++) acc[i] = 0ULL;

    if (e == 0) main_loop<0>(acc, rp);
    else        main_loop<1>(acc, rp);

    // ---- intra-warp reduce (parity-preserving xor strides 2,4,8,16) ----
    #pragma unroll 1
    for (int i = 0; i < NU; i++) {
        float2 f = u2f(acc[i]);
        #pragma unroll
        for (int o = 2; o <= 16; o <<= 1) {
            f.x += __shfl_xor_sync(0xFFFFFFFFu, f.x, o);
            f.y += __shfl_xor_sync(0xFFFFFFFFu, f.y, o);
        }
        // lane 0 holds parity-0 totals, lane 1 holds parity-1 totals
        if (lid < 2) {
            red[wid][lid * (2 * NU) + 2 * i]     = f.x;
            red[wid][lid * (2 * NU) + 2 * i + 1] = f.y;
        }
    }
    __syncthreads();

    // combine 8 warps: tot[p*80 + unit*2 + elem]
    if (tid < 4 * NU) {
        float s = 0.0f;
        #pragma unroll
        for (int w = 0; w < 8; w++) s += red[w][tid];
        tot[tid] = s;
    }
    __syncthreads();

    // ---- finalize: thread (m,n) ----
    {
        const int m  = tid >> 4;
        const int n  = tid & 15;
        const int mm = (m < n) ? m : n;
        const int nn = (m < n) ? n : m;
        const int H  = mm & 1;
        const int a  = mm >> 1;
        const float S = tot[H * 80 + (unit_base(a) + (nn >> 1) - a) * 2 + (nn & 1)];

        const int jm = m >> 1, jn = n >> 1;
        const float sm = tot[((jm >= 4) ? 80 : 0) + (36 + (jm & 3)) * 2 + (m & 1)];
        const float sn = tot[((jn >= 4) ? 80 : 0) + (36 + (jn & 3)) * 2 + (n & 1)];

        const float inv_T  = 1.0f / (float)T_DIM;
        const float inv_T1 = 1.0f / (float)(T_DIM - 1);
        out[(size_t)bc * 256 + tid] = (S - sm * sn * inv_T) * inv_T1;
    }
}

extern "C" void kernel_launch(void* const* d_in, const int* in_sizes, int n_in,
                              void* d_out, int out_size)
{
    const float* x = (const float*)d_in[0];
    float* out = (float*)d_out;
    cov_kernel<<<256, NTHREADS>>>(x, out);
}

// round 8
// speedup vs baseline: 1.4429x; 1.4429x over previous
#include <cuda_runtime.h>

// CovarianceLayer: x [64, 4, 8192, 16] fp32 -> cov [64, 4, 16, 16] fp32
// One CTA per (b,c), 256 threads, 2 CTAs/SM. No smem/barriers in the main loop.
// Lanes 2r and 2r+1 both load row r's full 64B (duplicate addresses merge inside
// each convergent warp LDG -> 1x traffic). Even lanes accumulate the even-m half
// of the 16x16 triangle, odd lanes the odd-m half — selected BRANCHLESSLY via
// SEL (the R7 version's per-lane branch diverged every warp for the whole loop,
// doubling issue+DRAM traffic). 40 packed-f32x2 accumulators, depth-2 prefetch.

#define T_DIM    8192
#define M_DIM    16
#define NTHREADS 256
#define NU       40   // f32x2 units per parity half: 36 triangle + 4 column-sum

typedef unsigned long long ull;

__device__ __forceinline__ void fma2(ull& d, ull a, ull b) {
    asm("fma.rn.f32x2 %0, %1, %2, %0;" : "+l"(d) : "l"(a), "l"(b));
}
__device__ __forceinline__ void add2(ull& d, ull a) {
    asm("add.rn.f32x2 %0, %1, %0;" : "+l"(d) : "l"(a));
}
__device__ __forceinline__ float2 u2f(ull u) {
    float2 f; asm("mov.b64 {%0,%1}, %2;" : "=f"(f.x), "=f"(f.y) : "l"(u)); return f;
}
__device__ __forceinline__ ull f2u(float lo, float hi) {
    ull u; asm("mov.b64 %0, {%1,%2};" : "=l"(u) : "f"(lo), "f"(hi)); return u;
}

__host__ __device__ __forceinline__ int unit_base(int a) { return 8 * a - a * (a - 1) / 2; }

__device__ __forceinline__ void loadrow(ull v[8], const ulonglong2* __restrict__ p) {
    ulonglong2 q0 = p[0], q1 = p[1], q2 = p[2], q3 = p[3];   // 4x LDG.128 (convergent)
    v[0] = q0.x; v[1] = q0.y; v[2] = q1.x; v[3] = q1.y;
    v[4] = q2.x; v[5] = q2.y; v[6] = q3.x; v[7] = q3.y;
}

// Branchless: `odd` is per-lane data, lowered to SEL/FSEL — no divergence.
__device__ __forceinline__ void accum_row(ull acc[NU], const ull v[8], bool odd) {
    #pragma unroll
    for (int a = 0; a < 8; a++) {            // m = 2a + parity
        float2 c = u2f(v[a]);
        const float vm = odd ? c.y : c.x;    // FSEL
        const ull bm = f2u(vm, vm);
        #pragma unroll
        for (int j = a; j < 8; j++)
            fma2(acc[unit_base(a) + j - a], bm, v[j]);   // (vm*v[2j], vm*v[2j+1])
    }
    #pragma unroll
    for (int j = 0; j < 4; j++)              // column sums: parity owns 4 pairs
        add2(acc[36 + j], odd ? v[4 + j] : v[j]);        // SELx2 + ADD2
}

__global__ void __launch_bounds__(NTHREADS, 2)
cov_kernel(const float* __restrict__ x, float* __restrict__ out)
{
    __shared__ float red[8][4 * NU];   // per-warp: [0..79]=parity0, [80..159]=parity1
    __shared__ float tot[4 * NU];      // 160 combined sums

    const int bc  = blockIdx.x;
    const int tid = threadIdx.x;
    const int wid = tid >> 5;
    const int lid = tid & 31;
    const bool odd = (lid & 1);        // parity (data-select only, never branched)
    const int lr  = lid >> 1;          // local row 0..15

    // rows handled: s*128 + wid*16 + lr, s = 0..63
    const ulonglong2* __restrict__ rp =
        reinterpret_cast<const ulonglong2*>(x + (size_t)bc * T_DIM * M_DIM)
        + (size_t)(wid * 16 + lr) * 4;

    ull acc[NU];
    #pragma unroll
    for (int i = 0; i < NU; i++) acc[i] = 0ULL;

    // depth-2 register prefetch pipeline, fully convergent
    {
        ull A[8], B[8];
        loadrow(A, rp);                          // row s=0
        loadrow(B, rp + 512);                    // row s=1 (512 ull2 = 128 rows)
        #pragma unroll 1
        for (int s = 0; s < 64; s += 2) {
            accum_row(acc, A, odd);
            if (s + 2 < 64) loadrow(A, rp + (size_t)(s + 2) * 512);
            accum_row(acc, B, odd);
            if (s + 3 < 64) loadrow(B, rp + (size_t)(s + 3) * 512);
        }
    }

    // ---- intra-warp reduce (parity-preserving xor strides 2,4,8,16) ----
    #pragma unroll 1
    for (int i = 0; i < NU; i++) {
        float2 f = u2f(acc[i]);
        #pragma unroll
        for (int o = 2; o <= 16; o <<= 1) {
            f.x += __shfl_xor_sync(0xFFFFFFFFu, f.x, o);
            f.y += __shfl_xor_sync(0xFFFFFFFFu, f.y, o);
        }
        // lane 0 holds parity-0 totals, lane 1 holds parity-1 totals
        if (lid < 2) {
            red[wid][lid * (2 * NU) + 2 * i]     = f.x;
            red[wid][lid * (2 * NU) + 2 * i + 1] = f.y;
        }
    }
    __syncthreads();

    // combine 8 warps: tot[p*80 + unit*2 + elem]
    if (tid < 4 * NU) {
        float s = 0.0f;
        #pragma unroll
        for (int w = 0; w < 8; w++) s += red[w][tid];
        tot[tid] = s;
    }
    __syncthreads();

    // ---- finalize: thread (m,n) ----
    {
        const int m  = tid >> 4;
        const int n  = tid & 15;
        const int mm = (m < n) ? m : n;
        const int nn = (m < n) ? n : m;
        const int H  = mm & 1;
        const int a  = mm >> 1;
        const float S = tot[H * 80 + (unit_base(a) + (nn >> 1) - a) * 2 + (nn & 1)];

        const int jm = m >> 1, jn = n >> 1;
        const float sm = tot[((jm >= 4) ? 80 : 0) + (36 + (jm & 3)) * 2 + (m & 1)];
        const float sn = tot[((jn >= 4) ? 80 : 0) + (36 + (jn & 3)) * 2 + (n & 1)];

        const float inv_T  = 1.0f / (float)T_DIM;
        const float inv_T1 = 1.0f / (float)(T_DIM - 1);
        out[(size_t)bc * 256 + tid] = (S - sm * sn * inv_T) * inv_T1;
    }
}

extern "C" void kernel_launch(void* const* d_in, const int* in_sizes, int n_in,
                              void* d_out, int out_size)
{
    const float* x = (const float*)d_in[0];
    float* out = (float*)d_out;
    cov_kernel<<<256, NTHREADS>>>(x, out);
}